// round 11
// baseline (speedup 1.0000x reference)
#include <cuda_runtime.h>
#include <cuda_fp16.h>
#include <math.h>
#include <stdint.h>

#define Rr   16
#define Cc   256
#define Bb   12
#define Ee   768
#define Hh   12
#define Dd   64
#define RD   1024
#define NTOK 49152
#define SCALING 0.03125f

// fp16 GEMM operands
__device__ __half g_xh [(size_t)NTOK*Ee];
__device__ __half g_wh [4][(size_t)Ee*Ee];
__device__ __half g_qh [(size_t)NTOK*Ee];
__device__ __half g_kh [(size_t)NTOK*Ee];
__device__ __half g_vh [(size_t)NTOK*Ee];
__device__ __half g_vth[(size_t)Hh*Bb*RD*Cc];
__device__ __half g_srh[(size_t)Hh*Bb*Cc*Cc];
__device__ __half g_ctxh[(size_t)NTOK*Ee];
// f32
__device__ float g_s [(size_t)Hh*Bb*Cc*Cc];
__device__ unsigned char g_buck[(size_t)Hh*Cc*Cc];

#define STAGE_BYTES  32768            // narrow: A 16KB + B 16KB
#define SMEM_DYN     (3*STAGE_BYTES)
#define WSTAGE_BYTES 49152            // wide: A 16KB + B 32KB
#define WSMEM_DYN    (3*WSTAGE_BYTES)

// ---------------- helpers ----------------
__device__ __forceinline__ uint32_t smem_u32(const void* p) {
    uint32_t a;
    asm("{ .reg .u64 t; cvta.to.shared.u64 t, %1; cvt.u32.u64 %0, t; }" : "=r"(a) : "l"(p));
    return a;
}
#define CP_ASYNC16(d, s) \
    asm volatile("cp.async.cg.shared.global [%0], [%1], 16;" :: "r"(d), "l"(s) : "memory")
#define CP_COMMIT() asm volatile("cp.async.commit_group;" ::: "memory")
#define CP_WAIT1()  asm volatile("cp.async.wait_group 1;" ::: "memory")
#define LDSM4(r, addr) \
    asm volatile("ldmatrix.sync.aligned.m8n8.x4.shared.b16 {%0,%1,%2,%3}, [%4];" \
        : "=r"((r)[0]), "=r"((r)[1]), "=r"((r)[2]), "=r"((r)[3]) : "r"(addr))
#define MMA_F16(d, a, b) \
    asm volatile("mma.sync.aligned.m16n8k16.row.col.f32.f16.f16.f32 " \
        "{%0,%1,%2,%3}, {%4,%5,%6,%7}, {%8,%9}, {%0,%1,%2,%3};" \
        : "+f"((d)[0]), "+f"((d)[1]), "+f"((d)[2]), "+f"((d)[3]) \
        : "r"((a)[0]), "r"((a)[1]), "r"((a)[2]), "r"((a)[3]), \
          "r"((b)[0]), "r"((b)[1]))

// ---------------- narrow GEMM core (128x128, 2 CTA/SM) — scores/ctx --------
__device__ __forceinline__ void gemm_mma_async(
    const char* a0, const char* b0, long arow, long brow,
    int NC, long roff, float acc[4][4][4])
{
    extern __shared__ uint32_t smem[];
    const uint32_t sbase = smem_u32(smem);
    const int t = threadIdx.x;
    const int lane = t & 31, wid = t >> 5;
    const int wm = wid >> 2, wn = wid & 3;

    uint32_t sts[4];
    {
        const int c16 = t & 7;
        #pragma unroll
        for (int i = 0; i < 4; i++) {
            int row = (t >> 3) + 32 * i;
            sts[i] = (uint32_t)(row * 128 + ((c16 ^ (row & 7)) << 4));
        }
    }
    uint32_t arel[4][4], brel[4][2];
    {
        #pragma unroll
        for (int mt = 0; mt < 4; mt++) {
            int row = wm * 64 + mt * 16 + (lane & 15);
            #pragma unroll
            for (int ks = 0; ks < 4; ks++) {
                int c16 = ks * 2 + (lane >> 4);
                arel[mt][ks] = (uint32_t)(row * 128 + ((c16 ^ (row & 7)) << 4));
            }
        }
        const int mm = lane >> 3;
        #pragma unroll
        for (int p = 0; p < 2; p++) {
            int row = wn * 32 + p * 16 + ((mm >> 1) << 3) + (lane & 7);
            #pragma unroll
            for (int ks = 0; ks < 4; ks++) {
                int c16 = ks * 2 + (mm & 1);
                brel[ks][p] = (uint32_t)(16384 + row * 128 + ((c16 ^ (row & 7)) << 4));
            }
        }
    }
    #pragma unroll
    for (int mt = 0; mt < 4; mt++)
        #pragma unroll
        for (int nt = 0; nt < 4; nt++)
            #pragma unroll
            for (int r = 0; r < 4; r++) acc[mt][nt][r] = 0.0f;

    #pragma unroll
    for (int s = 0; s < 2; s++) {
        const long o = (long)s * roff;
        const uint32_t d = sbase + (uint32_t)s * STAGE_BYTES;
        #pragma unroll
        for (int i = 0; i < 4; i++) {
            CP_ASYNC16(d + sts[i],          a0 + (long)(32 * i) * arow + o);
            CP_ASYNC16(d + 16384u + sts[i], b0 + (long)(32 * i) * brow + o);
        }
        CP_COMMIT();
    }

    int sc = 0;
    for (int c = 0; c < NC; c++) {
        CP_WAIT1();
        __syncthreads();
        if (c + 2 < NC) {
            const long o = (long)(c + 2) * roff;
            int sn = sc + 2; if (sn >= 3) sn -= 3;
            const uint32_t d = sbase + (uint32_t)sn * STAGE_BYTES;
            #pragma unroll
            for (int i = 0; i < 4; i++) {
                CP_ASYNC16(d + sts[i],          a0 + (long)(32 * i) * arow + o);
                CP_ASYNC16(d + 16384u + sts[i], b0 + (long)(32 * i) * brow + o);
            }
            CP_COMMIT();
        } else {
            CP_COMMIT();
        }

        const uint32_t sa = sbase + (uint32_t)sc * STAGE_BYTES;
        #pragma unroll
        for (int ks = 0; ks < 4; ks++) {
            uint32_t af[4][4], bf[4][2];
            #pragma unroll
            for (int mt = 0; mt < 4; mt++) LDSM4(af[mt], sa + arel[mt][ks]);
            #pragma unroll
            for (int p = 0; p < 2; p++) {
                uint32_t r4[4];
                LDSM4(r4, sa + brel[ks][p]);
                bf[2*p+0][0] = r4[0]; bf[2*p+0][1] = r4[1];
                bf[2*p+1][0] = r4[2]; bf[2*p+1][1] = r4[3];
            }
            #pragma unroll
            for (int mt = 0; mt < 4; mt++)
                #pragma unroll
                for (int nt = 0; nt < 4; nt++)
                    MMA_F16(acc[mt][nt], af[mt], bf[nt]);
        }
        if (++sc == 3) sc = 0;
    }
}

// ---------------- wide GEMM core (128x256, 1 CTA/SM) — proj/outproj --------
// 256 threads, warp grid 2(wm)x4(wn), warp tile 64x64.
// Stage: A 16KB (128 rows) + B 32KB (256 rows).  3 stages.
__device__ __forceinline__ void gemm_mma_wide(
    const char* a0, const char* b0, long arow, long brow,
    int NC, long roff, float acc[4][8][4])
{
    extern __shared__ uint32_t smem[];
    const uint32_t sbase = smem_u32(smem);
    const int t = threadIdx.x;
    const int lane = t & 31, wid = t >> 5;
    const int wm = wid >> 2, wn = wid & 3;

    uint32_t stsA[4], stsB[8];
    {
        const int rl = t >> 3, c16 = t & 7;
        #pragma unroll
        for (int i = 0; i < 4; i++) {
            int row = rl + 32 * i;
            stsA[i] = (uint32_t)(row * 128 + ((c16 ^ (row & 7)) << 4));
        }
        #pragma unroll
        for (int i = 0; i < 8; i++) {
            int row = rl + 32 * i;
            stsB[i] = (uint32_t)(16384 + row * 128 + ((c16 ^ (row & 7)) << 4));
        }
    }
    uint32_t arel[4][4], brel[4][4];
    {
        #pragma unroll
        for (int mt = 0; mt < 4; mt++) {
            int row = wm * 64 + mt * 16 + (lane & 15);
            #pragma unroll
            for (int ks = 0; ks < 4; ks++) {
                int c16 = ks * 2 + (lane >> 4);
                arel[mt][ks] = (uint32_t)(row * 128 + ((c16 ^ (row & 7)) << 4));
            }
        }
        const int mm = lane >> 3;
        #pragma unroll
        for (int p = 0; p < 4; p++) {
            int row = wn * 64 + p * 16 + ((mm >> 1) << 3) + (lane & 7);
            #pragma unroll
            for (int ks = 0; ks < 4; ks++) {
                int c16 = ks * 2 + (mm & 1);
                brel[ks][p] = (uint32_t)(16384 + row * 128 + ((c16 ^ (row & 7)) << 4));
            }
        }
    }
    #pragma unroll
    for (int mt = 0; mt < 4; mt++)
        #pragma unroll
        for (int nt = 0; nt < 8; nt++)
            #pragma unroll
            for (int r = 0; r < 4; r++) acc[mt][nt][r] = 0.0f;

    #pragma unroll
    for (int s = 0; s < 2; s++) {
        const long o = (long)s * roff;
        const uint32_t d = sbase + (uint32_t)s * WSTAGE_BYTES;
        #pragma unroll
        for (int i = 0; i < 4; i++)
            CP_ASYNC16(d + stsA[i], a0 + (long)(32 * i) * arow + o);
        #pragma unroll
        for (int i = 0; i < 8; i++)
            CP_ASYNC16(d + stsB[i], b0 + (long)(32 * i) * brow + o);
        CP_COMMIT();
    }

    int sc = 0;
    for (int c = 0; c < NC; c++) {
        CP_WAIT1();
        __syncthreads();
        if (c + 2 < NC) {
            const long o = (long)(c + 2) * roff;
            int sn = sc + 2; if (sn >= 3) sn -= 3;
            const uint32_t d = sbase + (uint32_t)sn * WSTAGE_BYTES;
            #pragma unroll
            for (int i = 0; i < 4; i++)
                CP_ASYNC16(d + stsA[i], a0 + (long)(32 * i) * arow + o);
            #pragma unroll
            for (int i = 0; i < 8; i++)
                CP_ASYNC16(d + stsB[i], b0 + (long)(32 * i) * brow + o);
            CP_COMMIT();
        } else {
            CP_COMMIT();
        }

        const uint32_t sa = sbase + (uint32_t)sc * WSTAGE_BYTES;
        #pragma unroll
        for (int ks = 0; ks < 4; ks++) {
            uint32_t af[4][4], bf[8][2];
            #pragma unroll
            for (int mt = 0; mt < 4; mt++) LDSM4(af[mt], sa + arel[mt][ks]);
            #pragma unroll
            for (int p = 0; p < 4; p++) {
                uint32_t r4[4];
                LDSM4(r4, sa + brel[ks][p]);
                bf[2*p+0][0] = r4[0]; bf[2*p+0][1] = r4[1];
                bf[2*p+1][0] = r4[2]; bf[2*p+1][1] = r4[3];
            }
            #pragma unroll
            for (int mt = 0; mt < 4; mt++)
                #pragma unroll
                for (int nt = 0; nt < 8; nt++)
                    MMA_F16(acc[mt][nt], af[mt], bf[nt]);
        }
        if (++sc == 3) sc = 0;
    }
}

#define EPI_IDX()                                                         \
    const int lane = threadIdx.x & 31, wid = threadIdx.x >> 5;            \
    const int wm = wid >> 2, wn = wid & 3;                                \
    const int grow0 = m0 + wm * 64 + (lane >> 2);                         \
    const int gcol0 = n0 + wn * 32 + (lane & 3) * 2;
#define EPI_IDX_W()                                                       \
    const int lane = threadIdx.x & 31, wid = threadIdx.x >> 5;            \
    const int wm = wid >> 2, wn = wid & 3;                                \
    const int grow0 = m0 + wm * 64 + (lane >> 2);                         \
    const int gcol0 = n0 + wn * 64 + (lane & 3) * 2;

// ---------------- small kernels ----------------
__device__ __forceinline__ int rel_bucket(int dist) {
    if (dist < 16) return dist;
    float v = logf(fmaxf((float)dist, 1.0f) * 0.0625f) * (15.0f / 8.047189562170502f);
    int b = 16 + (int)v;
    return b < 31 ? b : 31;
}
__global__ __launch_bounds__(256) void bucketize_kernel(const int* __restrict__ dist) {
    size_t i = (size_t)blockIdx.x * 256 + threadIdx.x;
    g_buck[i] = (unsigned char)rel_bucket(__ldg(&dist[i]));
}
struct h4 { __half2 a, b; };
__global__ __launch_bounds__(256) void pack_x_kernel(const float4* __restrict__ src) {
    size_t i = (size_t)blockIdx.x * 256 + threadIdx.x;
    float4 v = __ldg(&src[i]);
    h4 o; o.a = __floats2half2_rn(v.x, v.y); o.b = __floats2half2_rn(v.z, v.w);
    ((h4*)g_xh)[i] = o;
}
__global__ __launch_bounds__(256) void pack_w_kernel(
    const float4* __restrict__ w0, const float4* __restrict__ w1,
    const float4* __restrict__ w2, const float4* __restrict__ w3) {
    const int wsel = blockIdx.y;
    const float4* src = (wsel == 0) ? w0 : (wsel == 1) ? w1 : (wsel == 2) ? w2 : w3;
    size_t i = (size_t)blockIdx.x * 256 + threadIdx.x;
    float4 v = __ldg(&src[i]);
    h4 o; o.a = __floats2half2_rn(v.x, v.y); o.b = __floats2half2_rn(v.z, v.w);
    ((h4*)(g_wh[wsel]))[i] = o;
}

// ---------------- K1: QKV projection (wide tile) ----------------
__global__ __launch_bounds__(256, 1) void proj_mma(
    const float* __restrict__ bq, const float* __restrict__ bk, const float* __restrict__ bv)
{
    const int w  = blockIdx.z;
    const int n0 = blockIdx.x * 256;
    const int m0 = blockIdx.y * 128;
    const float* bias = (w == 0) ? bq : (w == 1) ? bk : bv;
    __half*      dst  = (w == 0) ? g_qh : (w == 1) ? g_kh : g_vh;
    const float  scale = (w == 0) ? SCALING : 1.0f;

    const int rl = threadIdx.x >> 3, c4 = threadIdx.x & 7;
    const char* a0 = (const char*)(g_xh + (size_t)(m0 + rl) * Ee) + c4 * 16;
    const char* b0 = (const char*)(g_wh[w] + (size_t)(n0 + rl) * Ee) + c4 * 16;

    float acc[4][8][4];
    gemm_mma_wide(a0, b0, (long)Ee*2, (long)Ee*2, 12, 128, acc);

    EPI_IDX_W();
    #pragma unroll
    for (int mt = 0; mt < 4; mt++) {
        const int rA = grow0 + mt * 16, rB = rA + 8;
        #pragma unroll
        for (int nt = 0; nt < 8; nt++) {
            const int cc = gcol0 + nt * 8;
            float2 bb = *(const float2*)(bias + cc);
            *(__half2*)(dst + (size_t)rA * Ee + cc) = __floats2half2_rn(
                (acc[mt][nt][0] + bb.x) * scale, (acc[mt][nt][1] + bb.y) * scale);
            *(__half2*)(dst + (size_t)rB * Ee + cc) = __floats2half2_rn(
                (acc[mt][nt][2] + bb.x) * scale, (acc[mt][nt][3] + bb.y) * scale);
        }
    }
}

// ---------------- K2: V transpose -> g_vth[hn][rd][j] ----------------
__global__ __launch_bounds__(256) void transpose_v_kernel()
{
    __shared__ __half2 tile[64][33];
    const int t = threadIdx.x;
    const int tx = t & 31, ty = t >> 5;
    const int jb = blockIdx.x, r = blockIdx.y, hn = blockIdx.z;
    const int h = hn / 12, n = hn % 12;

    #pragma unroll
    for (int i = 0; i < 8; i++) {
        int jl = ty * 8 + i;
        int j = jb * 64 + jl;
        tile[jl][tx] = *(const __half2*)(g_vh +
            ((size_t)(r * Cc + j) * Bb + n) * Ee + h * 64 + tx * 2);
    }
    __syncthreads();
    #pragma unroll
    for (int i = 0; i < 8; i++) {
        int dl = ty * 8 + i;
        __half2 v0 = tile[tx * 2 + 0][dl >> 1];
        __half2 v1 = tile[tx * 2 + 1][dl >> 1];
        __half a = (dl & 1) ? __high2half(v0) : __low2half(v0);
        __half b = (dl & 1) ? __high2half(v1) : __low2half(v1);
        *(__half2*)(g_vth + ((size_t)hn * RD + r * 64 + dl) * Cc
                    + jb * 64 + tx * 2) = __halves2half2(a, b);
    }
}

// ---------------- K3: scores + bucket bias (narrow tile) ----------------
__global__ __launch_bounds__(256, 2) void scores_mma(const float* __restrict__ rel_bias)
{
    const int n0 = blockIdx.x * 128;
    const int m0 = blockIdx.y * 128;
    const int hn = blockIdx.z;
    const int h = hn / 12, n = hn % 12;

    const int rl = threadIdx.x >> 3, c4 = threadIdx.x & 7;
    const char* a0 = (const char*)(g_qh + ((size_t)(m0 + rl) * Bb + n) * Ee + h * 64) + c4 * 16;
    const char* b0 = (const char*)(g_kh + ((size_t)(n0 + rl) * Bb + n) * Ee + h * 64) + c4 * 16;

    float acc[4][4][4];
    gemm_mma_async(a0, b0, (long)Bb*Ee*2, (long)Bb*Ee*2, 16, (long)Cc*Bb*Ee*2, acc);

    EPI_IDX();
    #pragma unroll
    for (int mt = 0; mt < 4; mt++) {
        const int iA = grow0 + mt * 16, iB = iA + 8;
        const unsigned char* bA = g_buck + ((size_t)h * Cc + iA) * Cc;
        const unsigned char* bB = g_buck + ((size_t)h * Cc + iB) * Cc;
        float* sA = g_s + ((size_t)hn * Cc + iA) * Cc;
        float* sB = g_s + ((size_t)hn * Cc + iB) * Cc;
        #pragma unroll
        for (int nt = 0; nt < 4; nt++) {
            const int cc = gcol0 + nt * 8;
            *(float2*)(sA + cc) = make_float2(
                acc[mt][nt][0] + __ldg(&rel_bias[bA[cc]   * Hh + n]),
                acc[mt][nt][1] + __ldg(&rel_bias[bA[cc+1] * Hh + n]));
            *(float2*)(sB + cc) = make_float2(
                acc[mt][nt][2] + __ldg(&rel_bias[bB[cc]   * Hh + n]),
                acc[mt][nt][3] + __ldg(&rel_bias[bB[cc+1] * Hh + n]));
        }
    }
}

// ---------------- K4: softmax, warp-per-row ----------------
__global__ __launch_bounds__(256) void softmax_kernel(float* __restrict__ dst)
{
    const int w = threadIdx.x >> 5, lane = threadIdx.x & 31;
    const size_t row = (size_t)blockIdx.x * 8 + w;
    const float* p = g_s + row * Cc;
    float*  pd = dst   + row * Cc;
    __half* pr = g_srh + row * Cc;

    float4 v0 = *(const float4*)(p + lane * 4);
    float4 v1 = *(const float4*)(p + 128 + lane * 4);
    float m = fmaxf(fmaxf(fmaxf(v0.x, v0.y), fmaxf(v0.z, v0.w)),
                    fmaxf(fmaxf(v1.x, v1.y), fmaxf(v1.z, v1.w)));
    #pragma unroll
    for (int o = 16; o > 0; o >>= 1) m = fmaxf(m, __shfl_xor_sync(~0u, m, o));

    float e0x = expf(v0.x - m), e0y = expf(v0.y - m), e0z = expf(v0.z - m), e0w = expf(v0.w - m);
    float e1x = expf(v1.x - m), e1y = expf(v1.y - m), e1z = expf(v1.z - m), e1w = expf(v1.w - m);
    float s = (e0x + e0y + e0z + e0w) + (e1x + e1y + e1z + e1w);
    #pragma unroll
    for (int o = 16; o > 0; o >>= 1) s += __shfl_xor_sync(~0u, s, o);
    const float inv = 1.0f / s;

    float4 o0 = make_float4(e0x*inv, e0y*inv, e0z*inv, e0w*inv);
    float4 o1 = make_float4(e1x*inv, e1y*inv, e1z*inv, e1w*inv);
    *(float4*)(pd + lane * 4) = o0;
    *(float4*)(pd + 128 + lane * 4) = o1;
    h4 q0, q1;
    q0.a = __floats2half2_rn(o0.x, o0.y); q0.b = __floats2half2_rn(o0.z, o0.w);
    q1.a = __floats2half2_rn(o1.x, o1.y); q1.b = __floats2half2_rn(o1.z, o1.w);
    *(h4*)(pr + lane * 4) = q0;
    *(h4*)(pr + 128 + lane * 4) = q1;
}

// ---------------- K5: context = P @ Vt (narrow tile) --------
__global__ __launch_bounds__(256, 2) void ctx_mma()
{
    const int n0 = blockIdx.x * 128;   // rd
    const int m0 = blockIdx.y * 128;   // i
    const int hn = blockIdx.z;
    const int h = hn / 12, n = hn % 12;

    const int rl = threadIdx.x >> 3, c4 = threadIdx.x & 7;
    const char* a0 = (const char*)(g_srh + ((size_t)hn * Cc + m0 + rl) * Cc) + c4 * 16;
    const char* b0 = (const char*)(g_vth + ((size_t)hn * RD + n0 + rl) * Cc) + c4 * 16;

    float acc[4][4][4];
    gemm_mma_async(a0, b0, (long)Cc*2, (long)Cc*2, 4, 128, acc);

    EPI_IDX();
    #pragma unroll
    for (int mt = 0; mt < 4; mt++) {
        const int iA = grow0 + mt * 16, iB = iA + 8;
        #pragma unroll
        for (int nt = 0; nt < 4; nt++) {
            const int cc = gcol0 + nt * 8;
            const int r = cc >> 6, d = cc & 63;
            __half* dA = g_ctxh + (((size_t)(r * Cc + iA)) * Bb + n) * Ee + h * 64 + d;
            __half* dB = g_ctxh + (((size_t)(r * Cc + iB)) * Bb + n) * Ee + h * 64 + d;
            *(__half2*)dA = __floats2half2_rn(acc[mt][nt][0], acc[mt][nt][1]);
            *(__half2*)dB = __floats2half2_rn(acc[mt][nt][2], acc[mt][nt][3]);
        }
    }
}

// ---------------- K6: output projection (wide tile, f32 out) ----------------
__global__ __launch_bounds__(256, 1) void outproj_mma(
    const float* __restrict__ bo, float* __restrict__ out)
{
    const int n0 = blockIdx.x * 256;
    const int m0 = blockIdx.y * 128;

    const int rl = threadIdx.x >> 3, c4 = threadIdx.x & 7;
    const char* a0 = (const char*)(g_ctxh + (size_t)(m0 + rl) * Ee) + c4 * 16;
    const char* b0 = (const char*)(g_wh[3] + (size_t)(n0 + rl) * Ee) + c4 * 16;

    float acc[4][8][4];
    gemm_mma_wide(a0, b0, (long)Ee*2, (long)Ee*2, 12, 128, acc);

    EPI_IDX_W();
    #pragma unroll
    for (int mt = 0; mt < 4; mt++) {
        const int rA = grow0 + mt * 16, rB = rA + 8;
        #pragma unroll
        for (int nt = 0; nt < 8; nt++) {
            const int cc = gcol0 + nt * 8;
            float2 bb = *(const float2*)(bo + cc);
            *(float2*)(out + (size_t)rA * Ee + cc) =
                make_float2(acc[mt][nt][0] + bb.x, acc[mt][nt][1] + bb.y);
            *(float2*)(out + (size_t)rB * Ee + cc) =
                make_float2(acc[mt][nt][2] + bb.x, acc[mt][nt][3] + bb.y);
        }
    }
}

// ---------------------------------------------------------------------------
extern "C" void kernel_launch(void* const* d_in, const int* in_sizes, int n_in,
                              void* d_out, int out_size)
{
    const float* x         = (const float*)d_in[0];
    const int*   distances = (const int*)  d_in[1];
    const float* Wq = (const float*)d_in[2];
    const float* bq = (const float*)d_in[3];
    const float* Wk = (const float*)d_in[4];
    const float* bk = (const float*)d_in[5];
    const float* Wv = (const float*)d_in[6];
    const float* bv = (const float*)d_in[7];
    const float* Wo = (const float*)d_in[8];
    const float* bo = (const float*)d_in[9];
    const float* rel_bias = (const float*)d_in[10];
    float* out = (float*)d_out;

    cudaFuncSetAttribute(proj_mma,    cudaFuncAttributeMaxDynamicSharedMemorySize, WSMEM_DYN);
    cudaFuncSetAttribute(scores_mma,  cudaFuncAttributeMaxDynamicSharedMemorySize, SMEM_DYN);
    cudaFuncSetAttribute(ctx_mma,     cudaFuncAttributeMaxDynamicSharedMemorySize, SMEM_DYN);
    cudaFuncSetAttribute(outproj_mma, cudaFuncAttributeMaxDynamicSharedMemorySize, WSMEM_DYN);

    float* d_gs;  cudaGetSymbolAddress((void**)&d_gs, g_s);

    pack_x_kernel<<<(unsigned)((size_t)NTOK*Ee/4/256), 256>>>((const float4*)x);
    pack_w_kernel<<<dim3(Ee*Ee/4/256, 4), 256>>>(
        (const float4*)Wq, (const float4*)Wk, (const float4*)Wv, (const float4*)Wo);
    bucketize_kernel<<<Hh*Cc*Cc/256, 256>>>(distances);

    proj_mma<<<dim3(3, NTOK/128, 3), 256, WSMEM_DYN>>>(bq, bk, bv);
    transpose_v_kernel<<<dim3(4, 16, 144), 256>>>();
    scores_mma<<<dim3(2, 2, 144), 256, SMEM_DYN>>>(rel_bias);

    const size_t out_elems   = (size_t)NTOK * Ee;
    const size_t probs_elems = (size_t)Hh * Bb * Cc * Cc;
    const bool want_probs = ((size_t)out_size >= out_elems + probs_elems);
    softmax_kernel<<<Hh*Bb*Cc/8, 256>>>(want_probs ? (out + out_elems) : d_gs);

    ctx_mma<<<dim3(8, 2, 144), 256, SMEM_DYN>>>();
    outproj_mma<<<dim3(3, NTOK/128), 256, WSMEM_DYN>>>(bo, out);
}

// round 12
// speedup vs baseline: 1.0932x; 1.0932x over previous
#include <cuda_runtime.h>
#include <cuda_fp16.h>
#include <math.h>
#include <stdint.h>

#define Rr   16
#define Cc   256
#define Bb   12
#define Ee   768
#define Hh   12
#define Dd   64
#define RD   1024
#define NTOK 49152
#define SCALING 0.03125f

// fp16 GEMM operands
__device__ __half g_xh [(size_t)NTOK*Ee];
__device__ __half g_wh [4][(size_t)Ee*Ee];
__device__ __half g_qh [(size_t)NTOK*Ee];
__device__ __half g_kh [(size_t)NTOK*Ee];
__device__ __half g_vh [(size_t)NTOK*Ee];
__device__ __half g_vth[(size_t)Hh*Bb*RD*Cc];
__device__ __half g_srh[(size_t)Hh*Bb*Cc*Cc];
__device__ __half g_ctxh[(size_t)NTOK*Ee];
// f32
__device__ float g_s [(size_t)Hh*Bb*Cc*Cc];
__device__ unsigned char g_buck[(size_t)Hh*Cc*Cc];

#define STAGE_BYTES 32768            // A 16KB + B 16KB (128 rows x 128B)
#define SMEM_DYN    (3*STAGE_BYTES)  // 3-stage pipeline

// ---------------- helpers ----------------
__device__ __forceinline__ uint32_t smem_u32(const void* p) {
    uint32_t a;
    asm("{ .reg .u64 t; cvta.to.shared.u64 t, %1; cvt.u32.u64 %0, t; }" : "=r"(a) : "l"(p));
    return a;
}
#define CP_ASYNC16(d, s) \
    asm volatile("cp.async.cg.shared.global [%0], [%1], 16;" :: "r"(d), "l"(s) : "memory")
#define CP_COMMIT() asm volatile("cp.async.commit_group;" ::: "memory")
#define CP_WAIT1()  asm volatile("cp.async.wait_group 1;" ::: "memory")
#define LDSM4(r, addr) \
    asm volatile("ldmatrix.sync.aligned.m8n8.x4.shared.b16 {%0,%1,%2,%3}, [%4];" \
        : "=r"((r)[0]), "=r"((r)[1]), "=r"((r)[2]), "=r"((r)[3]) : "r"(addr))
#define MMA_F16(d, a, b) \
    asm volatile("mma.sync.aligned.m16n8k16.row.col.f32.f16.f16.f32 " \
        "{%0,%1,%2,%3}, {%4,%5,%6,%7}, {%8,%9}, {%0,%1,%2,%3};" \
        : "+f"((d)[0]), "+f"((d)[1]), "+f"((d)[2]), "+f"((d)[3]) \
        : "r"((a)[0]), "r"((a)[1]), "r"((a)[2]), "r"((a)[3]), \
          "r"((b)[0]), "r"((b)[1]))

// ---------------- shared GEMM core (fp16, 256 threads, 2x4 warps) ----------
// Block 128(M) x 128(N).  K-chunk = 64 halfs = 128B/row.  Both operands
// K-contiguous (NT).  SMEM rows XOR-16B swizzled.  3-stage cp.async.
__device__ __forceinline__ void gemm_mma_async(
    const char* a0, const char* b0, long arow, long brow,
    int NC, long roff, float acc[4][4][4])
{
    extern __shared__ uint32_t smem[];
    const uint32_t sbase = smem_u32(smem);
    const int t = threadIdx.x;
    const int lane = t & 31, wid = t >> 5;
    const int wm = wid >> 2, wn = wid & 3;

    uint32_t sts[4];
    {
        const int c16 = t & 7;
        #pragma unroll
        for (int i = 0; i < 4; i++) {
            int row = (t >> 3) + 32 * i;
            sts[i] = (uint32_t)(row * 128 + ((c16 ^ (row & 7)) << 4));
        }
    }
    uint32_t arel[4][4], brel[4][2];
    {
        #pragma unroll
        for (int mt = 0; mt < 4; mt++) {
            int row = wm * 64 + mt * 16 + (lane & 15);
            #pragma unroll
            for (int ks = 0; ks < 4; ks++) {
                int c16 = ks * 2 + (lane >> 4);
                arel[mt][ks] = (uint32_t)(row * 128 + ((c16 ^ (row & 7)) << 4));
            }
        }
        const int mm = lane >> 3;
        #pragma unroll
        for (int p = 0; p < 2; p++) {
            int row = wn * 32 + p * 16 + ((mm >> 1) << 3) + (lane & 7);
            #pragma unroll
            for (int ks = 0; ks < 4; ks++) {
                int c16 = ks * 2 + (mm & 1);
                brel[ks][p] = (uint32_t)(16384 + row * 128 + ((c16 ^ (row & 7)) << 4));
            }
        }
    }
    #pragma unroll
    for (int mt = 0; mt < 4; mt++)
        #pragma unroll
        for (int nt = 0; nt < 4; nt++)
            #pragma unroll
            for (int r = 0; r < 4; r++) acc[mt][nt][r] = 0.0f;

    #pragma unroll
    for (int s = 0; s < 2; s++) {
        const long o = (long)s * roff;
        const uint32_t d = sbase + (uint32_t)s * STAGE_BYTES;
        #pragma unroll
        for (int i = 0; i < 4; i++) {
            CP_ASYNC16(d + sts[i],          a0 + (long)(32 * i) * arow + o);
            CP_ASYNC16(d + 16384u + sts[i], b0 + (long)(32 * i) * brow + o);
        }
        CP_COMMIT();
    }

    int sc = 0;
    for (int c = 0; c < NC; c++) {
        CP_WAIT1();
        __syncthreads();
        if (c + 2 < NC) {
            const long o = (long)(c + 2) * roff;
            int sn = sc + 2; if (sn >= 3) sn -= 3;
            const uint32_t d = sbase + (uint32_t)sn * STAGE_BYTES;
            #pragma unroll
            for (int i = 0; i < 4; i++) {
                CP_ASYNC16(d + sts[i],          a0 + (long)(32 * i) * arow + o);
                CP_ASYNC16(d + 16384u + sts[i], b0 + (long)(32 * i) * brow + o);
            }
            CP_COMMIT();
        } else {
            CP_COMMIT();
        }

        const uint32_t sa = sbase + (uint32_t)sc * STAGE_BYTES;
        #pragma unroll
        for (int ks = 0; ks < 4; ks++) {
            uint32_t af[4][4], bf[4][2];
            #pragma unroll
            for (int mt = 0; mt < 4; mt++) LDSM4(af[mt], sa + arel[mt][ks]);
            #pragma unroll
            for (int p = 0; p < 2; p++) {
                uint32_t r4[4];
                LDSM4(r4, sa + brel[ks][p]);
                bf[2*p+0][0] = r4[0]; bf[2*p+0][1] = r4[1];
                bf[2*p+1][0] = r4[2]; bf[2*p+1][1] = r4[3];
            }
            #pragma unroll
            for (int mt = 0; mt < 4; mt++)
                #pragma unroll
                for (int nt = 0; nt < 4; nt++)
                    MMA_F16(acc[mt][nt], af[mt], bf[nt]);
        }
        if (++sc == 3) sc = 0;
    }
}

#define EPI_IDX()                                                         \
    const int lane = threadIdx.x & 31, wid = threadIdx.x >> 5;            \
    const int wm = wid >> 2, wn = wid & 3;                                \
    const int grow0 = m0 + wm * 64 + (lane >> 2);                         \
    const int gcol0 = n0 + wn * 32 + (lane & 3) * 2;

// ---------------- fused prolog: pack x, pack W[4], bucketize -------------
__device__ __forceinline__ int rel_bucket(int dist) {
    if (dist < 16) return dist;
    float v = logf(fmaxf((float)dist, 1.0f) * 0.0625f) * (15.0f / 8.047189562170502f);
    int b = 16 + (int)v;
    return b < 31 ? b : 31;
}
struct h4 { __half2 a, b; };
#define XF4 ((size_t)NTOK*Ee/4)          // 9,437,184
#define WF4 ((size_t)Ee*Ee/4)            //   147,456
#define DI4 ((size_t)Hh*Cc*Cc/4)         //   196,608
#define PROLOG_BLOCKS ((unsigned)((XF4 + 4*WF4 + DI4) / 256))  // 39936

__global__ __launch_bounds__(256) void prolog_kernel(
    const float4* __restrict__ x,
    const float4* __restrict__ w0, const float4* __restrict__ w1,
    const float4* __restrict__ w2, const float4* __restrict__ w3,
    const int4* __restrict__ dist)
{
    size_t i = (size_t)blockIdx.x * 256 + threadIdx.x;
    if (i < XF4) {
        float4 v = __ldg(&x[i]);
        h4 o; o.a = __floats2half2_rn(v.x, v.y); o.b = __floats2half2_rn(v.z, v.w);
        ((h4*)g_xh)[i] = o;
    } else if (i < XF4 + 4*WF4) {
        size_t j = i - XF4;
        int ws = (int)(j / WF4);
        size_t k = j - (size_t)ws * WF4;
        const float4* src = (ws == 0) ? w0 : (ws == 1) ? w1 : (ws == 2) ? w2 : w3;
        float4 v = __ldg(&src[k]);
        h4 o; o.a = __floats2half2_rn(v.x, v.y); o.b = __floats2half2_rn(v.z, v.w);
        ((h4*)(g_wh[ws]))[k] = o;
    } else {
        size_t j = i - XF4 - 4*WF4;
        int4 d = __ldg(&dist[j]);
        uchar4 o;
        o.x = (unsigned char)rel_bucket(d.x);
        o.y = (unsigned char)rel_bucket(d.y);
        o.z = (unsigned char)rel_bucket(d.z);
        o.w = (unsigned char)rel_bucket(d.w);
        ((uchar4*)g_buck)[j] = o;
    }
}

// ---------------- K1: QKV projection ----------------
__global__ __launch_bounds__(256, 2) void proj_mma(
    const float* __restrict__ bq, const float* __restrict__ bk, const float* __restrict__ bv)
{
    const int w  = blockIdx.z;
    const int n0 = blockIdx.x * 128;
    const int m0 = blockIdx.y * 128;
    const float* bias = (w == 0) ? bq : (w == 1) ? bk : bv;
    __half*      dst  = (w == 0) ? g_qh : (w == 1) ? g_kh : g_vh;
    const float  scale = (w == 0) ? SCALING : 1.0f;

    const int rl = threadIdx.x >> 3, c4 = threadIdx.x & 7;
    const char* a0 = (const char*)(g_xh + (size_t)(m0 + rl) * Ee) + c4 * 16;
    const char* b0 = (const char*)(g_wh[w] + (size_t)(n0 + rl) * Ee) + c4 * 16;

    float acc[4][4][4];
    gemm_mma_async(a0, b0, (long)Ee*2, (long)Ee*2, 12, 128, acc);

    EPI_IDX();
    #pragma unroll
    for (int mt = 0; mt < 4; mt++) {
        const int rA = grow0 + mt * 16, rB = rA + 8;
        #pragma unroll
        for (int nt = 0; nt < 4; nt++) {
            const int cc = gcol0 + nt * 8;
            float2 bb = *(const float2*)(bias + cc);
            *(__half2*)(dst + (size_t)rA * Ee + cc) = __floats2half2_rn(
                (acc[mt][nt][0] + bb.x) * scale, (acc[mt][nt][1] + bb.y) * scale);
            *(__half2*)(dst + (size_t)rB * Ee + cc) = __floats2half2_rn(
                (acc[mt][nt][2] + bb.x) * scale, (acc[mt][nt][3] + bb.y) * scale);
        }
    }
}

// ---------------- K2: V transpose -> g_vth[hn][rd][j] ----------------
__global__ __launch_bounds__(256) void transpose_v_kernel()
{
    __shared__ __half2 tile[64][33];
    const int t = threadIdx.x;
    const int tx = t & 31, ty = t >> 5;
    const int jb = blockIdx.x, r = blockIdx.y, hn = blockIdx.z;
    const int h = hn / 12, n = hn % 12;

    #pragma unroll
    for (int i = 0; i < 8; i++) {
        int jl = ty * 8 + i;
        int j = jb * 64 + jl;
        tile[jl][tx] = *(const __half2*)(g_vh +
            ((size_t)(r * Cc + j) * Bb + n) * Ee + h * 64 + tx * 2);
    }
    __syncthreads();
    #pragma unroll
    for (int i = 0; i < 8; i++) {
        int dl = ty * 8 + i;
        __half2 v0 = tile[tx * 2 + 0][dl >> 1];
        __half2 v1 = tile[tx * 2 + 1][dl >> 1];
        __half a = (dl & 1) ? __high2half(v0) : __low2half(v0);
        __half b = (dl & 1) ? __high2half(v1) : __low2half(v1);
        *(__half2*)(g_vth + ((size_t)hn * RD + r * 64 + dl) * Cc
                    + jb * 64 + tx * 2) = __halves2half2(a, b);
    }
}

// ---------------- K3: scores + bucket bias ----------------
__global__ __launch_bounds__(256, 2) void scores_mma(const float* __restrict__ rel_bias)
{
    const int n0 = blockIdx.x * 128;
    const int m0 = blockIdx.y * 128;
    const int hn = blockIdx.z;
    const int h = hn / 12, n = hn % 12;

    const int rl = threadIdx.x >> 3, c4 = threadIdx.x & 7;
    const char* a0 = (const char*)(g_qh + ((size_t)(m0 + rl) * Bb + n) * Ee + h * 64) + c4 * 16;
    const char* b0 = (const char*)(g_kh + ((size_t)(n0 + rl) * Bb + n) * Ee + h * 64) + c4 * 16;

    float acc[4][4][4];
    gemm_mma_async(a0, b0, (long)Bb*Ee*2, (long)Bb*Ee*2, 16, (long)Cc*Bb*Ee*2, acc);

    EPI_IDX();
    #pragma unroll
    for (int mt = 0; mt < 4; mt++) {
        const int iA = grow0 + mt * 16, iB = iA + 8;
        const unsigned char* bA = g_buck + ((size_t)h * Cc + iA) * Cc;
        const unsigned char* bB = g_buck + ((size_t)h * Cc + iB) * Cc;
        float* sA = g_s + ((size_t)hn * Cc + iA) * Cc;
        float* sB = g_s + ((size_t)hn * Cc + iB) * Cc;
        #pragma unroll
        for (int nt = 0; nt < 4; nt++) {
            const int cc = gcol0 + nt * 8;
            *(float2*)(sA + cc) = make_float2(
                acc[mt][nt][0] + __ldg(&rel_bias[bA[cc]   * Hh + n]),
                acc[mt][nt][1] + __ldg(&rel_bias[bA[cc+1] * Hh + n]));
            *(float2*)(sB + cc) = make_float2(
                acc[mt][nt][2] + __ldg(&rel_bias[bB[cc]   * Hh + n]),
                acc[mt][nt][3] + __ldg(&rel_bias[bB[cc+1] * Hh + n]));
        }
    }
}

// ---------------- K4: softmax, warp-per-row ----------------
__global__ __launch_bounds__(256) void softmax_kernel(float* __restrict__ dst)
{
    const int w = threadIdx.x >> 5, lane = threadIdx.x & 31;
    const size_t row = (size_t)blockIdx.x * 8 + w;
    const float* p = g_s + row * Cc;
    float*  pd = dst   + row * Cc;
    __half* pr = g_srh + row * Cc;

    float4 v0 = *(const float4*)(p + lane * 4);
    float4 v1 = *(const float4*)(p + 128 + lane * 4);
    float m = fmaxf(fmaxf(fmaxf(v0.x, v0.y), fmaxf(v0.z, v0.w)),
                    fmaxf(fmaxf(v1.x, v1.y), fmaxf(v1.z, v1.w)));
    #pragma unroll
    for (int o = 16; o > 0; o >>= 1) m = fmaxf(m, __shfl_xor_sync(~0u, m, o));

    float e0x = expf(v0.x - m), e0y = expf(v0.y - m), e0z = expf(v0.z - m), e0w = expf(v0.w - m);
    float e1x = expf(v1.x - m), e1y = expf(v1.y - m), e1z = expf(v1.z - m), e1w = expf(v1.w - m);
    float s = (e0x + e0y + e0z + e0w) + (e1x + e1y + e1z + e1w);
    #pragma unroll
    for (int o = 16; o > 0; o >>= 1) s += __shfl_xor_sync(~0u, s, o);
    const float inv = 1.0f / s;

    float4 o0 = make_float4(e0x*inv, e0y*inv, e0z*inv, e0w*inv);
    float4 o1 = make_float4(e1x*inv, e1y*inv, e1z*inv, e1w*inv);
    *(float4*)(pd + lane * 4) = o0;
    *(float4*)(pd + 128 + lane * 4) = o1;
    h4 q0, q1;
    q0.a = __floats2half2_rn(o0.x, o0.y); q0.b = __floats2half2_rn(o0.z, o0.w);
    q1.a = __floats2half2_rn(o1.x, o1.y); q1.b = __floats2half2_rn(o1.z, o1.w);
    *(h4*)(pr + lane * 4) = q0;
    *(h4*)(pr + 128 + lane * 4) = q1;
}

// ---------------- K5: context = P @ Vt -> token layout fp16 --------
__global__ __launch_bounds__(256, 2) void ctx_mma()
{
    const int n0 = blockIdx.x * 128;   // rd
    const int m0 = blockIdx.y * 128;   // i
    const int hn = blockIdx.z;
    const int h = hn / 12, n = hn % 12;

    const int rl = threadIdx.x >> 3, c4 = threadIdx.x & 7;
    const char* a0 = (const char*)(g_srh + ((size_t)hn * Cc + m0 + rl) * Cc) + c4 * 16;
    const char* b0 = (const char*)(g_vth + ((size_t)hn * RD + n0 + rl) * Cc) + c4 * 16;

    float acc[4][4][4];
    gemm_mma_async(a0, b0, (long)Cc*2, (long)Cc*2, 4, 128, acc);

    EPI_IDX();
    #pragma unroll
    for (int mt = 0; mt < 4; mt++) {
        const int iA = grow0 + mt * 16, iB = iA + 8;
        #pragma unroll
        for (int nt = 0; nt < 4; nt++) {
            const int cc = gcol0 + nt * 8;
            const int r = cc >> 6, d = cc & 63;
            __half* dA = g_ctxh + (((size_t)(r * Cc + iA)) * Bb + n) * Ee + h * 64 + d;
            __half* dB = g_ctxh + (((size_t)(r * Cc + iB)) * Bb + n) * Ee + h * 64 + d;
            *(__half2*)dA = __floats2half2_rn(acc[mt][nt][0], acc[mt][nt][1]);
            *(__half2*)dB = __floats2half2_rn(acc[mt][nt][2], acc[mt][nt][3]);
        }
    }
}

// ---------------- K6: output projection (f32 out) ----------------
__global__ __launch_bounds__(256, 2) void outproj_mma(
    const float* __restrict__ bo, float* __restrict__ out)
{
    const int n0 = blockIdx.x * 128;
    const int m0 = blockIdx.y * 128;

    const int rl = threadIdx.x >> 3, c4 = threadIdx.x & 7;
    const char* a0 = (const char*)(g_ctxh + (size_t)(m0 + rl) * Ee) + c4 * 16;
    const char* b0 = (const char*)(g_wh[3] + (size_t)(n0 + rl) * Ee) + c4 * 16;

    float acc[4][4][4];
    gemm_mma_async(a0, b0, (long)Ee*2, (long)Ee*2, 12, 128, acc);

    EPI_IDX();
    #pragma unroll
    for (int mt = 0; mt < 4; mt++) {
        const int rA = grow0 + mt * 16, rB = rA + 8;
        #pragma unroll
        for (int nt = 0; nt < 4; nt++) {
            const int cc = gcol0 + nt * 8;
            float2 bb = *(const float2*)(bo + cc);
            *(float2*)(out + (size_t)rA * Ee + cc) =
                make_float2(acc[mt][nt][0] + bb.x, acc[mt][nt][1] + bb.y);
            *(float2*)(out + (size_t)rB * Ee + cc) =
                make_float2(acc[mt][nt][2] + bb.x, acc[mt][nt][3] + bb.y);
        }
    }
}

// ---------------------------------------------------------------------------
extern "C" void kernel_launch(void* const* d_in, const int* in_sizes, int n_in,
                              void* d_out, int out_size)
{
    const float* x         = (const float*)d_in[0];
    const int*   distances = (const int*)  d_in[1];
    const float* Wq = (const float*)d_in[2];
    const float* bq = (const float*)d_in[3];
    const float* Wk = (const float*)d_in[4];
    const float* bk = (const float*)d_in[5];
    const float* Wv = (const float*)d_in[6];
    const float* bv = (const float*)d_in[7];
    const float* Wo = (const float*)d_in[8];
    const float* bo = (const float*)d_in[9];
    const float* rel_bias = (const float*)d_in[10];
    float* out = (float*)d_out;

    cudaFuncSetAttribute(proj_mma,    cudaFuncAttributeMaxDynamicSharedMemorySize, SMEM_DYN);
    cudaFuncSetAttribute(scores_mma,  cudaFuncAttributeMaxDynamicSharedMemorySize, SMEM_DYN);
    cudaFuncSetAttribute(ctx_mma,     cudaFuncAttributeMaxDynamicSharedMemorySize, SMEM_DYN);
    cudaFuncSetAttribute(outproj_mma, cudaFuncAttributeMaxDynamicSharedMemorySize, SMEM_DYN);

    float* d_gs;  cudaGetSymbolAddress((void**)&d_gs, g_s);

    prolog_kernel<<<PROLOG_BLOCKS, 256>>>(
        (const float4*)x,
        (const float4*)Wq, (const float4*)Wk, (const float4*)Wv, (const float4*)Wo,
        (const int4*)distances);

    proj_mma<<<dim3(6, NTOK/128, 3), 256, SMEM_DYN>>>(bq, bk, bv);
    transpose_v_kernel<<<dim3(4, 16, 144), 256>>>();
    scores_mma<<<dim3(2, 2, 144), 256, SMEM_DYN>>>(rel_bias);

    const size_t out_elems   = (size_t)NTOK * Ee;
    const size_t probs_elems = (size_t)Hh * Bb * Cc * Cc;
    const bool want_probs = ((size_t)out_size >= out_elems + probs_elems);
    softmax_kernel<<<Hh*Bb*Cc/8, 256>>>(want_probs ? (out + out_elems) : d_gs);

    ctx_mma<<<dim3(8, 2, 144), 256, SMEM_DYN>>>();
    outproj_mma<<<dim3(6, NTOK/128), 256, SMEM_DYN>>>(bo, out);
}

// round 16
// speedup vs baseline: 1.0953x; 1.0020x over previous
#include <cuda_runtime.h>
#include <cuda_fp16.h>
#include <math.h>
#include <stdint.h>

#define Rr   16
#define Cc   256
#define Bb   12
#define Ee   768
#define Hh   12
#define Dd   64
#define RD   1024
#define NTOK 49152
#define SCALING 0.03125f

// fp16 GEMM operands
__device__ __half g_xh [(size_t)NTOK*Ee];
__device__ __half g_wh [4][(size_t)Ee*Ee];
__device__ __half g_qh [(size_t)NTOK*Ee];
__device__ __half g_kh [(size_t)NTOK*Ee];
__device__ __half g_vh [(size_t)NTOK*Ee];
__device__ __half g_vth[(size_t)Hh*Bb*RD*Cc];
__device__ __half g_srh[(size_t)Hh*Bb*Cc*Cc];
__device__ __half g_ctxh[(size_t)NTOK*Ee];
// f32
__device__ float g_s [(size_t)Hh*Bb*Cc*Cc];
__device__ unsigned char g_buck[(size_t)Hh*Cc*Cc];

#define STAGE_BYTES 32768            // A 16KB + B 16KB (128 rows x 128B)
#define SMEM_DYN    (3*STAGE_BYTES)  // 3-stage pipeline

// ---------------- helpers ----------------
__device__ __forceinline__ uint32_t smem_u32(const void* p) {
    uint32_t a;
    asm("{ .reg .u64 t; cvta.to.shared.u64 t, %1; cvt.u32.u64 %0, t; }" : "=r"(a) : "l"(p));
    return a;
}
#define CP_ASYNC16(d, s) \
    asm volatile("cp.async.cg.shared.global [%0], [%1], 16;" :: "r"(d), "l"(s) : "memory")
#define CP_COMMIT() asm volatile("cp.async.commit_group;" ::: "memory")
#define CP_WAIT1()  asm volatile("cp.async.wait_group 1;" ::: "memory")
#define LDSM4(r, addr) \
    asm volatile("ldmatrix.sync.aligned.m8n8.x4.shared.b16 {%0,%1,%2,%3}, [%4];" \
        : "=r"((r)[0]), "=r"((r)[1]), "=r"((r)[2]), "=r"((r)[3]) : "r"(addr))
#define MMA_F16(d, a, b) \
    asm volatile("mma.sync.aligned.m16n8k16.row.col.f32.f16.f16.f32 " \
        "{%0,%1,%2,%3}, {%4,%5,%6,%7}, {%8,%9}, {%0,%1,%2,%3};" \
        : "+f"((d)[0]), "+f"((d)[1]), "+f"((d)[2]), "+f"((d)[3]) \
        : "r"((a)[0]), "r"((a)[1]), "r"((a)[2]), "r"((a)[3]), \
          "r"((b)[0]), "r"((b)[1]))

// ---------------- shared GEMM core (fp16, 256 threads, 2x4 warps) ----------
// Block 128(M) x 128(N).  K-chunk = 64 halfs = 128B/row.  3-stage cp.async.
// Ordering: wait(chunk c) -> __syncthreads -> prefetch stage (c+2)%3.
// The barrier is load-bearing: it separates the last reader of stage
// (c-1)%3 (slow warps still in iteration c-1) from the prefetch write to
// that same stage ((c+2) % 3 == (c-1) % 3).  Do NOT hoist the prefetch.
__device__ __forceinline__ void gemm_mma_async(
    const char* a0, const char* b0, long arow, long brow,
    int NC, long roff, float acc[4][4][4])
{
    extern __shared__ uint32_t smem[];
    const uint32_t sbase = smem_u32(smem);
    const int t = threadIdx.x;
    const int lane = t & 31, wid = t >> 5;
    const int wm = wid >> 2, wn = wid & 3;

    uint32_t sts[4];
    {
        const int c16 = t & 7;
        #pragma unroll
        for (int i = 0; i < 4; i++) {
            int row = (t >> 3) + 32 * i;
            sts[i] = (uint32_t)(row * 128 + ((c16 ^ (row & 7)) << 4));
        }
    }
    uint32_t arel[4][4], brel[4][2];
    {
        #pragma unroll
        for (int mt = 0; mt < 4; mt++) {
            int row = wm * 64 + mt * 16 + (lane & 15);
            #pragma unroll
            for (int ks = 0; ks < 4; ks++) {
                int c16 = ks * 2 + (lane >> 4);
                arel[mt][ks] = (uint32_t)(row * 128 + ((c16 ^ (row & 7)) << 4));
            }
        }
        const int mm = lane >> 3;
        #pragma unroll
        for (int p = 0; p < 2; p++) {
            int row = wn * 32 + p * 16 + ((mm >> 1) << 3) + (lane & 7);
            #pragma unroll
            for (int ks = 0; ks < 4; ks++) {
                int c16 = ks * 2 + (mm & 1);
                brel[ks][p] = (uint32_t)(16384 + row * 128 + ((c16 ^ (row & 7)) << 4));
            }
        }
    }
    #pragma unroll
    for (int mt = 0; mt < 4; mt++)
        #pragma unroll
        for (int nt = 0; nt < 4; nt++)
            #pragma unroll
            for (int r = 0; r < 4; r++) acc[mt][nt][r] = 0.0f;

    #pragma unroll
    for (int s = 0; s < 2; s++) {
        const long o = (long)s * roff;
        const uint32_t d = sbase + (uint32_t)s * STAGE_BYTES;
        #pragma unroll
        for (int i = 0; i < 4; i++) {
            CP_ASYNC16(d + sts[i],          a0 + (long)(32 * i) * arow + o);
            CP_ASYNC16(d + 16384u + sts[i], b0 + (long)(32 * i) * brow + o);
        }
        CP_COMMIT();
    }

    int sc = 0;
    for (int c = 0; c < NC; c++) {
        CP_WAIT1();
        __syncthreads();
        if (c + 2 < NC) {
            const long o = (long)(c + 2) * roff;
            int sn = sc + 2; if (sn >= 3) sn -= 3;
            const uint32_t d = sbase + (uint32_t)sn * STAGE_BYTES;
            #pragma unroll
            for (int i = 0; i < 4; i++) {
                CP_ASYNC16(d + sts[i],          a0 + (long)(32 * i) * arow + o);
                CP_ASYNC16(d + 16384u + sts[i], b0 + (long)(32 * i) * brow + o);
            }
            CP_COMMIT();
        } else {
            CP_COMMIT();
        }

        const uint32_t sa = sbase + (uint32_t)sc * STAGE_BYTES;
        #pragma unroll
        for (int ks = 0; ks < 4; ks++) {
            uint32_t af[4][4], bf[4][2];
            #pragma unroll
            for (int mt = 0; mt < 4; mt++) LDSM4(af[mt], sa + arel[mt][ks]);
            #pragma unroll
            for (int p = 0; p < 2; p++) {
                uint32_t r4[4];
                LDSM4(r4, sa + brel[ks][p]);
                bf[2*p+0][0] = r4[0]; bf[2*p+0][1] = r4[1];
                bf[2*p+1][0] = r4[2]; bf[2*p+1][1] = r4[3];
            }
            #pragma unroll
            for (int mt = 0; mt < 4; mt++)
                #pragma unroll
                for (int nt = 0; nt < 4; nt++)
                    MMA_F16(acc[mt][nt], af[mt], bf[nt]);
        }
        if (++sc == 3) sc = 0;
    }
}

#define EPI_IDX()                                                         \
    const int lane = threadIdx.x & 31, wid = threadIdx.x >> 5;            \
    const int wm = wid >> 2, wn = wid & 3;                                \
    const int grow0 = m0 + wm * 64 + (lane >> 2);                         \
    const int gcol0 = n0 + wn * 32 + (lane & 3) * 2;

// ---------------- fused prolog: pack x, pack W[4], bucketize -------------
__device__ __forceinline__ int rel_bucket(int dist) {
    if (dist < 16) return dist;
    float v = logf(fmaxf((float)dist, 1.0f) * 0.0625f) * (15.0f / 8.047189562170502f);
    int b = 16 + (int)v;
    return b < 31 ? b : 31;
}
struct h4 { __half2 a, b; };
#define XF4 ((size_t)NTOK*Ee/4)
#define WF4 ((size_t)Ee*Ee/4)
#define DI4 ((size_t)Hh*Cc*Cc/4)
#define PROLOG_BLOCKS ((unsigned)((XF4 + 4*WF4 + DI4) / 256))

__global__ __launch_bounds__(256) void prolog_kernel(
    const float4* __restrict__ x,
    const float4* __restrict__ w0, const float4* __restrict__ w1,
    const float4* __restrict__ w2, const float4* __restrict__ w3,
    const int4* __restrict__ dist)
{
    size_t i = (size_t)blockIdx.x * 256 + threadIdx.x;
    if (i < XF4) {
        float4 v = __ldg(&x[i]);
        h4 o; o.a = __floats2half2_rn(v.x, v.y); o.b = __floats2half2_rn(v.z, v.w);
        ((h4*)g_xh)[i] = o;
    } else if (i < XF4 + 4*WF4) {
        size_t j = i - XF4;
        int ws = (int)(j / WF4);
        size_t k = j - (size_t)ws * WF4;
        const float4* src = (ws == 0) ? w0 : (ws == 1) ? w1 : (ws == 2) ? w2 : w3;
        float4 v = __ldg(&src[k]);
        h4 o; o.a = __floats2half2_rn(v.x, v.y); o.b = __floats2half2_rn(v.z, v.w);
        ((h4*)(g_wh[ws]))[k] = o;
    } else {
        size_t j = i - XF4 - 4*WF4;
        int4 d = __ldg(&dist[j]);
        uchar4 o;
        o.x = (unsigned char)rel_bucket(d.x);
        o.y = (unsigned char)rel_bucket(d.y);
        o.z = (unsigned char)rel_bucket(d.z);
        o.w = (unsigned char)rel_bucket(d.w);
        ((uchar4*)g_buck)[j] = o;
    }
}

// ---------------- K1: QKV projection ----------------
__global__ __launch_bounds__(256, 2) void proj_mma(
    const float* __restrict__ bq, const float* __restrict__ bk, const float* __restrict__ bv)
{
    const int w  = blockIdx.z;
    const int n0 = blockIdx.x * 128;
    const int m0 = blockIdx.y * 128;
    const float* bias = (w == 0) ? bq : (w == 1) ? bk : bv;
    __half*      dst  = (w == 0) ? g_qh : (w == 1) ? g_kh : g_vh;
    const float  scale = (w == 0) ? SCALING : 1.0f;

    const int rl = threadIdx.x >> 3, c4 = threadIdx.x & 7;
    const char* a0 = (const char*)(g_xh + (size_t)(m0 + rl) * Ee) + c4 * 16;
    const char* b0 = (const char*)(g_wh[w] + (size_t)(n0 + rl) * Ee) + c4 * 16;

    float acc[4][4][4];
    gemm_mma_async(a0, b0, (long)Ee*2, (long)Ee*2, 12, 128, acc);

    EPI_IDX();
    #pragma unroll
    for (int mt = 0; mt < 4; mt++) {
        const int rA = grow0 + mt * 16, rB = rA + 8;
        #pragma unroll
        for (int nt = 0; nt < 4; nt++) {
            const int cc = gcol0 + nt * 8;
            float2 bb = *(const float2*)(bias + cc);
            *(__half2*)(dst + (size_t)rA * Ee + cc) = __floats2half2_rn(
                (acc[mt][nt][0] + bb.x) * scale, (acc[mt][nt][1] + bb.y) * scale);
            *(__half2*)(dst + (size_t)rB * Ee + cc) = __floats2half2_rn(
                (acc[mt][nt][2] + bb.x) * scale, (acc[mt][nt][3] + bb.y) * scale);
        }
    }
}

// ---------------- K3: scores + bucket bias ----------------
__global__ __launch_bounds__(256, 2) void scores_mma(const float* __restrict__ rel_bias)
{
    const int n0 = blockIdx.x * 128;
    const int m0 = blockIdx.y * 128;
    const int hn = blockIdx.z;
    const int h = hn / 12, n = hn % 12;

    const int rl = threadIdx.x >> 3, c4 = threadIdx.x & 7;
    const char* a0 = (const char*)(g_qh + ((size_t)(m0 + rl) * Bb + n) * Ee + h * 64) + c4 * 16;
    const char* b0 = (const char*)(g_kh + ((size_t)(n0 + rl) * Bb + n) * Ee + h * 64) + c4 * 16;

    float acc[4][4][4];
    gemm_mma_async(a0, b0, (long)Bb*Ee*2, (long)Bb*Ee*2, 16, (long)Cc*Bb*Ee*2, acc);

    EPI_IDX();
    #pragma unroll
    for (int mt = 0; mt < 4; mt++) {
        const int iA = grow0 + mt * 16, iB = iA + 8;
        const unsigned char* bA = g_buck + ((size_t)h * Cc + iA) * Cc;
        const unsigned char* bB = g_buck + ((size_t)h * Cc + iB) * Cc;
        float* sA = g_s + ((size_t)hn * Cc + iA) * Cc;
        float* sB = g_s + ((size_t)hn * Cc + iB) * Cc;
        #pragma unroll
        for (int nt = 0; nt < 4; nt++) {
            const int cc = gcol0 + nt * 8;
            *(float2*)(sA + cc) = make_float2(
                acc[mt][nt][0] + __ldg(&rel_bias[bA[cc]   * Hh + n]),
                acc[mt][nt][1] + __ldg(&rel_bias[bA[cc+1] * Hh + n]));
            *(float2*)(sB + cc) = make_float2(
                acc[mt][nt][2] + __ldg(&rel_bias[bB[cc]   * Hh + n]),
                acc[mt][nt][3] + __ldg(&rel_bias[bB[cc+1] * Hh + n]));
        }
    }
}

// ---------------- K4: fused mid kernel — softmax + V transpose ----------
#define SMX_BLOCKS (Hh*Bb*Cc/8)        // 4608
#define TRN_BLOCKS (4*16*144)          // 9216
__global__ __launch_bounds__(256) void mid_kernel(float* __restrict__ dst)
{
    if (blockIdx.x < SMX_BLOCKS) {
        const int w = threadIdx.x >> 5, lane = threadIdx.x & 31;
        const size_t row = (size_t)blockIdx.x * 8 + w;
        const float* p = g_s + row * Cc;
        float*  pd = dst   + row * Cc;
        __half* pr = g_srh + row * Cc;

        float4 v0 = *(const float4*)(p + lane * 4);
        float4 v1 = *(const float4*)(p + 128 + lane * 4);
        float m = fmaxf(fmaxf(fmaxf(v0.x, v0.y), fmaxf(v0.z, v0.w)),
                        fmaxf(fmaxf(v1.x, v1.y), fmaxf(v1.z, v1.w)));
        #pragma unroll
        for (int o = 16; o > 0; o >>= 1) m = fmaxf(m, __shfl_xor_sync(~0u, m, o));

        float e0x = expf(v0.x - m), e0y = expf(v0.y - m), e0z = expf(v0.z - m), e0w = expf(v0.w - m);
        float e1x = expf(v1.x - m), e1y = expf(v1.y - m), e1z = expf(v1.z - m), e1w = expf(v1.w - m);
        float s = (e0x + e0y + e0z + e0w) + (e1x + e1y + e1z + e1w);
        #pragma unroll
        for (int o = 16; o > 0; o >>= 1) s += __shfl_xor_sync(~0u, s, o);
        const float inv = 1.0f / s;

        float4 o0 = make_float4(e0x*inv, e0y*inv, e0z*inv, e0w*inv);
        float4 o1 = make_float4(e1x*inv, e1y*inv, e1z*inv, e1w*inv);
        *(float4*)(pd + lane * 4) = o0;
        *(float4*)(pd + 128 + lane * 4) = o1;
        h4 q0, q1;
        q0.a = __floats2half2_rn(o0.x, o0.y); q0.b = __floats2half2_rn(o0.z, o0.w);
        q1.a = __floats2half2_rn(o1.x, o1.y); q1.b = __floats2half2_rn(o1.z, o1.w);
        *(h4*)(pr + lane * 4) = q0;
        *(h4*)(pr + 128 + lane * 4) = q1;
    } else {
        __shared__ __half2 tile[64][33];
        const int b = blockIdx.x - SMX_BLOCKS;
        const int jb = b & 3, r = (b >> 2) & 15, hn = b >> 6;
        const int h = hn / 12, n = hn % 12;
        const int t = threadIdx.x;
        const int tx = t & 31, ty = t >> 5;

        #pragma unroll
        for (int i = 0; i < 8; i++) {
            int jl = ty * 8 + i;
            int j = jb * 64 + jl;
            tile[jl][tx] = *(const __half2*)(g_vh +
                ((size_t)(r * Cc + j) * Bb + n) * Ee + h * 64 + tx * 2);
        }
        __syncthreads();
        #pragma unroll
        for (int i = 0; i < 8; i++) {
            int dl = ty * 8 + i;
            __half2 v0 = tile[tx * 2 + 0][dl >> 1];
            __half2 v1 = tile[tx * 2 + 1][dl >> 1];
            __half a = (dl & 1) ? __high2half(v0) : __low2half(v0);
            __half bq = (dl & 1) ? __high2half(v1) : __low2half(v1);
            *(__half2*)(g_vth + ((size_t)hn * RD + r * 64 + dl) * Cc
                        + jb * 64 + tx * 2) = __halves2half2(a, bq);
        }
    }
}

// ---------------- K5: context = P @ Vt -> token layout fp16 --------
__global__ __launch_bounds__(256, 2) void ctx_mma()
{
    const int n0 = blockIdx.x * 128;   // rd
    const int m0 = blockIdx.y * 128;   // i
    const int hn = blockIdx.z;
    const int h = hn / 12, n = hn % 12;

    const int rl = threadIdx.x >> 3, c4 = threadIdx.x & 7;
    const char* a0 = (const char*)(g_srh + ((size_t)hn * Cc + m0 + rl) * Cc) + c4 * 16;
    const char* b0 = (const char*)(g_vth + ((size_t)hn * RD + n0 + rl) * Cc) + c4 * 16;

    float acc[4][4][4];
    gemm_mma_async(a0, b0, (long)Cc*2, (long)Cc*2, 4, 128, acc);

    EPI_IDX();
    #pragma unroll
    for (int mt = 0; mt < 4; mt++) {
        const int iA = grow0 + mt * 16, iB = iA + 8;
        #pragma unroll
        for (int nt = 0; nt < 4; nt++) {
            const int cc = gcol0 + nt * 8;
            const int r = cc >> 6, d = cc & 63;
            __half* dA = g_ctxh + (((size_t)(r * Cc + iA)) * Bb + n) * Ee + h * 64 + d;
            __half* dB = g_ctxh + (((size_t)(r * Cc + iB)) * Bb + n) * Ee + h * 64 + d;
            *(__half2*)dA = __floats2half2_rn(acc[mt][nt][0], acc[mt][nt][1]);
            *(__half2*)dB = __floats2half2_rn(acc[mt][nt][2], acc[mt][nt][3]);
        }
    }
}

// ---------------- K6: output projection (f32 out) ----------------
__global__ __launch_bounds__(256, 2) void outproj_mma(
    const float* __restrict__ bo, float* __restrict__ out)
{
    const int n0 = blockIdx.x * 128;
    const int m0 = blockIdx.y * 128;

    const int rl = threadIdx.x >> 3, c4 = threadIdx.x & 7;
    const char* a0 = (const char*)(g_ctxh + (size_t)(m0 + rl) * Ee) + c4 * 16;
    const char* b0 = (const char*)(g_wh[3] + (size_t)(n0 + rl) * Ee) + c4 * 16;

    float acc[4][4][4];
    gemm_mma_async(a0, b0, (long)Ee*2, (long)Ee*2, 12, 128, acc);

    EPI_IDX();
    #pragma unroll
    for (int mt = 0; mt < 4; mt++) {
        const int rA = grow0 + mt * 16, rB = rA + 8;
        #pragma unroll
        for (int nt = 0; nt < 4; nt++) {
            const int cc = gcol0 + nt * 8;
            float2 bb = *(const float2*)(bo + cc);
            *(float2*)(out + (size_t)rA * Ee + cc) =
                make_float2(acc[mt][nt][0] + bb.x, acc[mt][nt][1] + bb.y);
            *(float2*)(out + (size_t)rB * Ee + cc) =
                make_float2(acc[mt][nt][2] + bb.x, acc[mt][nt][3] + bb.y);
        }
    }
}

// ---------------------------------------------------------------------------
extern "C" void kernel_launch(void* const* d_in, const int* in_sizes, int n_in,
                              void* d_out, int out_size)
{
    const float* x         = (const float*)d_in[0];
    const int*   distances = (const int*)  d_in[1];
    const float* Wq = (const float*)d_in[2];
    const float* bq = (const float*)d_in[3];
    const float* Wk = (const float*)d_in[4];
    const float* bk = (const float*)d_in[5];
    const float* Wv = (const float*)d_in[6];
    const float* bv = (const float*)d_in[7];
    const float* Wo = (const float*)d_in[8];
    const float* bo = (const float*)d_in[9];
    const float* rel_bias = (const float*)d_in[10];
    float* out = (float*)d_out;

    cudaFuncSetAttribute(proj_mma,    cudaFuncAttributeMaxDynamicSharedMemorySize, SMEM_DYN);
    cudaFuncSetAttribute(scores_mma,  cudaFuncAttributeMaxDynamicSharedMemorySize, SMEM_DYN);
    cudaFuncSetAttribute(ctx_mma,     cudaFuncAttributeMaxDynamicSharedMemorySize, SMEM_DYN);
    cudaFuncSetAttribute(outproj_mma, cudaFuncAttributeMaxDynamicSharedMemorySize, SMEM_DYN);

    float* d_gs;  cudaGetSymbolAddress((void**)&d_gs, g_s);

    prolog_kernel<<<PROLOG_BLOCKS, 256>>>(
        (const float4*)x,
        (const float4*)Wq, (const float4*)Wk, (const float4*)Wv, (const float4*)Wo,
        (const int4*)distances);

    proj_mma<<<dim3(6, NTOK/128, 3), 256, SMEM_DYN>>>(bq, bk, bv);
    scores_mma<<<dim3(2, 2, 144), 256, SMEM_DYN>>>(rel_bias);

    const size_t out_elems   = (size_t)NTOK * Ee;
    const size_t probs_elems = (size_t)Hh * Bb * Cc * Cc;
    const bool want_probs = ((size_t)out_size >= out_elems + probs_elems);
    mid_kernel<<<SMX_BLOCKS + TRN_BLOCKS, 256>>>(want_probs ? (out + out_elems) : d_gs);

    ctx_mma<<<dim3(8, 2, 144), 256, SMEM_DYN>>>();
    outproj_mma<<<dim3(6, NTOK/128), 256, SMEM_DYN>>>(bo, out);
}